// round 1
// baseline (speedup 1.0000x reference)
#include <cuda_runtime.h>
#include <cuda_bf16.h>
#include <math.h>

// ---------------------------------------------------------------------------
// SemanticConsistencyLoss: per-class feature centers for src/trg, Frobenius
// norm of the difference.
//
// Shapes (B=1): features [256, 262144] fp32 (channel-major), labels [262144] i32.
//
// Plan:
//  K1 (accum): grid (74 chunks, 2 tensors), 256 threads, 1 CTA/SM, 189KB smem.
//     - thread t exclusively owns channel t's 150-bin fp32 sum table in smem
//       (row stride 151 -> bank-conflict-free; NO atomics on data).
//     - per 32-pixel tile: coalesced float4 global loads -> transposed smem
//       tile (row stride 33 -> conflict-free), then 32 owned accumulates.
//     - next tile prefetched into registers during accumulate (hides DRAM lat).
//     - per-CTA label histogram (tiny smem atomics, integer-exact in fp32).
//     - partial sums/counts written to __device__ scratch.
//  K2 (reduce): 150 blocks x 256 thr: sum 74 partials per tensor, form center
//     diff, deterministic block tree-reduction of d^2 -> per-class sumsq.
//  K3 (final): single thread sums 150 values in fixed order, sqrt -> d_out[0].
// ---------------------------------------------------------------------------

#define NUM_CLASSES 150
#define CH          256
#define NPIX        (512 * 512)
#define CHUNKS      74
#define PPC         3584          // pixels per chunk (74*3584 >= NPIX)
#define TPB         256
#define TSTR        151           // table row stride (gcd(151,32)=1)
#define TLSTR       33            // tile row stride  (gcd(33,32)=1)
#define NTILES_MAX  (PPC / 32)    // 112

__device__ float g_psums[2][CHUNKS][NUM_CLASSES][CH];  // ~22.7 MB scratch
__device__ float g_pcnts[2][CHUNKS][NUM_CLASSES];
__device__ float g_csq[NUM_CLASSES];

// smem layout (floats): table[256*151] | tile[256*33] | lbl[32 ints] | cnt[150]
#define SMEM_FLOATS (CH * TSTR + CH * TLSTR + 32 + NUM_CLASSES)
#define SMEM_BYTES  (SMEM_FLOATS * 4)

__global__ void __launch_bounds__(TPB, 1)
accum_kernel(const float* __restrict__ src, const float* __restrict__ trg,
             const int* __restrict__ slab, const int* __restrict__ tlab) {
    extern __shared__ float sm[];
    float* table = sm;                           // CH * TSTR
    float* tile  = sm + CH * TSTR;               // CH * TLSTR
    int*   lbl   = (int*)(tile + CH * TLSTR);    // 32
    float* cnt   = (float*)(lbl + 32);           // NUM_CLASSES

    const int tsel  = blockIdx.y;
    const int chunk = blockIdx.x;
    const float* __restrict__ F = tsel ? trg : src;
    const int*   __restrict__ L = tsel ? tlab : slab;
    const int tid = threadIdx.x;

    // zero owned tables + histogram
    for (int i = tid; i < CH * TSTR; i += TPB) table[i] = 0.0f;
    if (tid < NUM_CLASSES) cnt[tid] = 0.0f;
    __syncthreads();

    const int pbase  = chunk * PPC;
    const int ntiles = min(NTILES_MAX, (NPIX - pbase) / 32);  // 112 or 16

    float4 r[8];
    int lblreg = 0;

    // prefetch tile 0 (coalesced: q=tid+256*i -> channel q>>3, pixel-quad q&7)
    {
        const int p0 = pbase;
#pragma unroll
        for (int i = 0; i < 8; ++i) {
            int q = tid + TPB * i;
            int c = q >> 3, j4 = q & 7;
            r[i] = *(const float4*)(F + (size_t)c * NPIX + p0 + j4 * 4);
        }
        if (tid < 32) lblreg = L[p0 + tid];
    }

    for (int ti = 0; ti < ntiles; ++ti) {
        // ---- store phase: registers -> transposed smem tile (conflict-free) ----
#pragma unroll
        for (int i = 0; i < 8; ++i) {
            int q = tid + TPB * i;
            int c = q >> 3, j4 = q & 7;
            float* d = tile + c * TLSTR + j4 * 4;
            d[0] = r[i].x; d[1] = r[i].y; d[2] = r[i].z; d[3] = r[i].w;
        }
        if (tid < 32) {
            lbl[tid] = lblreg;
            atomicAdd(&cnt[lblreg], 1.0f);   // integer-valued -> order-exact
        }
        __syncthreads();

        // ---- prefetch next tile into registers (overlaps accumulate) ----
        if (ti + 1 < ntiles) {
            const int p0 = pbase + (ti + 1) * 32;
#pragma unroll
            for (int i = 0; i < 8; ++i) {
                int q = tid + TPB * i;
                int c = q >> 3, j4 = q & 7;
                r[i] = *(const float4*)(F + (size_t)c * NPIX + p0 + j4 * 4);
            }
            if (tid < 32) lblreg = L[p0 + tid];
        }

        // ---- accumulate phase: thread tid owns channel tid, no atomics ----
        const float* trow = tile + tid * TLSTR;
        float* tab = table + tid * TSTR;
#pragma unroll
        for (int j = 0; j < 32; ++j) {
            tab[lbl[j]] += trow[j];
        }
        __syncthreads();
    }

    // ---- write partials: [class][channel], coalesced ----
    float* outS = &g_psums[tsel][chunk][0][0];
    for (int i = tid; i < NUM_CLASSES * CH; i += TPB) {
        int c  = i >> 8;      // / 256
        int ch = i & 255;     // % 256
        outS[i] = table[ch * TSTR + c];
    }
    if (tid < NUM_CLASSES) g_pcnts[tsel][chunk][tid] = cnt[tid];
}

__global__ void reduce_kernel() {
    const int c  = blockIdx.x;    // class
    const int ch = threadIdx.x;   // channel

    float ss = 0.0f, st = 0.0f;
#pragma unroll 2
    for (int k = 0; k < CHUNKS; ++k) {
        ss += g_psums[0][k][c][ch];
        st += g_psums[1][k][c][ch];
    }
    float cs = 0.0f, ctn = 0.0f;
    for (int k = 0; k < CHUNKS; ++k) {
        cs  += g_pcnts[0][k][c];
        ctn += g_pcnts[1][k][c];
    }
    float d = ss / (cs + 1e-8f) - st / (ctn + 1e-8f);

    __shared__ float red[CH];
    red[ch] = d * d;
    __syncthreads();
#pragma unroll
    for (int s = CH / 2; s > 0; s >>= 1) {
        if (ch < s) red[ch] += red[ch + s];
        __syncthreads();
    }
    if (ch == 0) g_csq[c] = red[0];
}

__global__ void final_kernel(float* out) {
    if (threadIdx.x == 0) {
        float s = 0.0f;
        for (int c = 0; c < NUM_CLASSES; ++c) s += g_csq[c];
        out[0] = sqrtf(s);
    }
}

extern "C" void kernel_launch(void* const* d_in, const int* in_sizes, int n_in,
                              void* d_out, int out_size) {
    const float* src = (const float*)d_in[0];   // src_fea  [1,256,512,512] f32
    const float* trg = (const float*)d_in[1];   // trg_fea
    const int*   sl  = (const int*)d_in[2];     // src_labels [1,512,512] i32
    const int*   tl  = (const int*)d_in[3];     // trg_pseudo_labels
    float* out = (float*)d_out;

    cudaFuncSetAttribute(accum_kernel,
                         cudaFuncAttributeMaxDynamicSharedMemorySize,
                         SMEM_BYTES);

    dim3 grid(CHUNKS, 2);
    accum_kernel<<<grid, TPB, SMEM_BYTES>>>(src, trg, sl, tl);
    reduce_kernel<<<NUM_CLASSES, CH>>>();
    final_kernel<<<1, 32>>>(out);
}